// round 1
// baseline (speedup 1.0000x reference)
#include <cuda_runtime.h>
#include <math.h>
#include <stdint.h>

// ---------------- problem constants ----------------
#define NN   10000
#define EE   160000
#define GGG  64
#define DDIM 480
#define HH   4
#define LLAY 6
#define DHH  120
#define NBB  128
#define SHN  9

static const float AVG_DEG_F   = 15.57930850982666f;
static const float AVG_NODES_F = 18.03065905448718f;

// ---------------- scratch buffer (static device memory; no runtime alloc) ----
constexpr size_t SZ_SH   = (size_t)EE * SHN;
constexpr size_t SZ_RBF  = (size_t)EE * NBB;
constexpr size_t SZ_G0   = (size_t)EE;
constexpr size_t SZ_GATE = (size_t)LLAY * EE * HH;
constexpr size_t SZ_ND   = (size_t)NN * DDIM;
constexpr size_t SZ_HID  = (size_t)NN * 2 * DDIM;
constexpr size_t SZ_LOG  = (size_t)EE * HH;
constexpr size_t SZ_NH   = (size_t)NN * HH;

constexpr size_t O_SH   = 0;
constexpr size_t O_RBF  = O_SH   + SZ_SH;
constexpr size_t O_G0   = O_RBF  + SZ_RBF;
constexpr size_t O_GATE = O_G0   + SZ_G0;
constexpr size_t O_X    = O_GATE + SZ_GATE;
constexpr size_t O_QN   = O_X    + SZ_ND;
constexpr size_t O_KN   = O_QN   + SZ_ND;
constexpr size_t O_VN   = O_KN   + SZ_ND;
constexpr size_t O_AGG  = O_VN   + SZ_ND;
constexpr size_t O_TMP  = O_AGG  + SZ_ND;
constexpr size_t O_HN   = O_TMP  + SZ_ND;
constexpr size_t O_HID  = O_HN   + SZ_ND;
constexpr size_t O_LOG  = O_HID  + SZ_HID;
constexpr size_t O_M    = O_LOG  + SZ_LOG;
constexpr size_t O_DEN  = O_M    + SZ_NH;
constexpr size_t TOTAL_F = O_DEN + SZ_NH;

__device__ float g_buf[TOTAL_F];

// ---------------- helpers ----------------
__device__ __forceinline__ float warpSum(float v) {
#pragma unroll
    for (int o = 16; o; o >>= 1) v += __shfl_down_sync(0xffffffffu, v, o);
    return v;
}

__device__ __forceinline__ float siluf(float x) {
    return x / (1.0f + expf(-x));
}

__device__ __forceinline__ void atomicMaxFloat(float* addr, float val) {
    int old = __float_as_int(*addr);
    while (__int_as_float(old) < val) {
        int prev = atomicCAS((int*)addr, old, __float_as_int(val));
        if (prev == old) break;
        old = prev;
    }
}

// ---------------- edge geometry: sh (E,9) + rbf (E,128) -------------------
__global__ void edge_geom_kernel(const float* __restrict__ pos,
                                 const int* __restrict__ src,
                                 const int* __restrict__ dst,
                                 float* __restrict__ sh,
                                 float* __restrict__ rbf) {
    int e = (blockIdx.x * blockDim.x + threadIdx.x) >> 5;
    int lane = threadIdx.x & 31;
    if (e >= EE) return;
    int s = src[e], d = dst[e];
    float vx = pos[s * 3 + 0] - pos[d * 3 + 0];
    float vy = pos[s * 3 + 1] - pos[d * 3 + 1];
    float vz = pos[s * 3 + 2] - pos[d * 3 + 2];
    float r = sqrtf(vx * vx + vy * vy + vz * vz);
    float rr = r + 1e-12f;
    float x = vx / rr, y = vy / rr, z = vz / rr;
    if (lane == 0) {
        const float s3 = 1.7320508075688772f;   // sqrt(3)
        const float s5 = 2.23606797749979f;     // sqrt(5)
        const float s15 = 3.872983346207417f;   // sqrt(15)
        float* o = sh + (size_t)e * SHN;
        o[0] = 1.0f;
        o[1] = s3 * x;
        o[2] = s3 * y;
        o[3] = s3 * z;
        o[4] = s15 * x * y;
        o[5] = s15 * y * z;
        o[6] = 0.5f * s5 * (3.0f * z * z - 1.0f);
        o[7] = s15 * x * z;
        o[8] = 0.5f * s15 * (x * x - y * y);
    }
    const float width = 5.0f / 128.0f;      // CUTOFF / NB
    const float cstep = 5.0f / 127.0f;      // linspace(0, CUTOFF, NB) step
#pragma unroll
    for (int t = 0; t < 4; t++) {
        int i = t * 32 + lane;
        float c = cstep * (float)i;
        float u = (r - c) / width;
        rbf[(size_t)e * NBB + i] = expf(-u * u);
    }
}

// ------------- radial MLP: out = (silu(silu(rbf@W1)@W2))@W3 , warp/edge ----
__global__ void edge_mlp_kernel(const float* __restrict__ rbf,
                                const float* __restrict__ W1,  // (128,64)
                                const float* __restrict__ W2,  // (64,64)
                                const float* __restrict__ W3,  // (64,OD)
                                float* __restrict__ out, int OD) {
    int e = (blockIdx.x * blockDim.x + threadIdx.x) >> 5;
    int lane = threadIdx.x & 31;
    if (e >= EE) return;
    const float* r = rbf + (size_t)e * NBB;
    float h0 = 0.f, h1 = 0.f;  // hidden units j = lane, lane+32
    for (int k = 0; k < NBB; k++) {
        float rk = __ldg(&r[k]);
        h0 += rk * W1[k * 64 + lane];
        h1 += rk * W1[k * 64 + lane + 32];
    }
    h0 = siluf(h0);
    h1 = siluf(h1);
    float g0 = 0.f, g1 = 0.f;
#pragma unroll
    for (int j = 0; j < 64; j++) {
        float hj = __shfl_sync(0xffffffffu, (j < 32) ? h0 : h1, j & 31);
        g0 += hj * W2[j * 64 + lane];
        g1 += hj * W2[j * 64 + lane + 32];
    }
    g0 = siluf(g0);
    g1 = siluf(g1);
    for (int o = 0; o < OD; o++) {
        float p = g0 * W3[lane * OD + o] + g1 * W3[(lane + 32) * OD + o];
        p = warpSum(p);
        if (lane == 0) out[(size_t)e * OD + o] = p;
    }
}

// -------------- x = atom_table[node_atom] ----------------------------------
__global__ void embed_kernel(const float* __restrict__ atom_table,
                             const int* __restrict__ node_atom,
                             float* __restrict__ x) {
    int i = blockIdx.x * blockDim.x + threadIdx.x;
    if (i >= NN * DDIM) return;
    int n = i / DDIM, dd = i - n * DDIM;
    x[i] = atom_table[node_atom[n] * DDIM + dd];
}

// -------------- x += (sh@Wdeg)*g0 / sqrt(AVG_DEG), scattered to dst --------
__global__ void deg_kernel(const float* __restrict__ sh,
                           const float* __restrict__ Wdeg,  // (9,480)
                           const float* __restrict__ g0,
                           const int* __restrict__ dst,
                           float* __restrict__ x, float scale) {
    int e = (blockIdx.x * blockDim.x + threadIdx.x) >> 5;
    int lane = threadIdx.x & 31;
    if (e >= EE) return;
    int d = dst[e];
    float shreg[SHN];
#pragma unroll
    for (int i = 0; i < SHN; i++) shreg[i] = sh[(size_t)e * SHN + i];
    float g = g0[e] * scale;
#pragma unroll
    for (int t = 0; t < 15; t++) {
        int dd = t * 32 + lane;
        float val = 0.f;
#pragma unroll
        for (int si = 0; si < SHN; si++) val += shreg[si] * Wdeg[si * DDIM + dd];
        atomicAdd(&x[(size_t)d * DDIM + dd], val * g);
    }
}

// -------------- per-layer init: agg=0, m=-inf, den=0 -----------------------
__global__ void init_layer_kernel(float* __restrict__ agg,
                                  float* __restrict__ m,
                                  float* __restrict__ den) {
    int i = blockIdx.x * blockDim.x + threadIdx.x;
    if (i < NN * DDIM) agg[i] = 0.f;
    if (i < NN * HH) {
        m[i] = __int_as_float(0xff800000);  // -inf
        den[i] = 0.f;
    }
}

// -------------- logits[e,h] = inv*gate * q[dst]·(k[src]+sh@Wsh) ------------
__global__ void logits_kernel(const float* __restrict__ qn,
                              const float* __restrict__ kn,
                              const float* __restrict__ sh,
                              const float* __restrict__ Wsh_l,  // (9,480)
                              const float* __restrict__ gate_l, // (E,4)
                              const int* __restrict__ src,
                              const int* __restrict__ dst,
                              float* __restrict__ logits,
                              float* __restrict__ m) {
    int e = (blockIdx.x * blockDim.x + threadIdx.x) >> 5;
    int lane = threadIdx.x & 31;
    if (e >= EE) return;
    int s = src[e], d = dst[e];
    float shreg[SHN];
#pragma unroll
    for (int i = 0; i < SHN; i++) shreg[i] = sh[(size_t)e * SHN + i];
    const float* qrow = qn + (size_t)d * DDIM;
    const float* krow = kn + (size_t)s * DDIM;
    const float inv = 0.09128709291752768f;  // 1/sqrt(120)
#pragma unroll
    for (int h = 0; h < HH; h++) {
        float acc = 0.f;
#pragma unroll
        for (int t = 0; t < 4; t++) {
            int j = t * 32 + lane;
            if (j < DHH) {
                int dd = h * DHH + j;
                float kv = krow[dd];
                float shk = 0.f;
#pragma unroll
                for (int si = 0; si < SHN; si++) shk += shreg[si] * Wsh_l[si * DDIM + dd];
                acc += qrow[dd] * (kv + shk);
            }
        }
        acc = warpSum(acc);
        if (lane == 0) {
            float lg = acc * inv * gate_l[(size_t)e * HH + h];
            logits[(size_t)e * HH + h] = lg;
            atomicMaxFloat(&m[(size_t)d * HH + h], lg);
        }
    }
}

// -------------- a = exp(logit - m[dst]); den[dst] += a ----------------------
__global__ void expden_kernel(float* __restrict__ logits,
                              const float* __restrict__ m,
                              float* __restrict__ den,
                              const int* __restrict__ dst) {
    int i = blockIdx.x * blockDim.x + threadIdx.x;
    if (i >= EE * HH) return;
    int e = i >> 2, h = i & 3;
    int d = dst[e];
    float a = expf(logits[i] - m[d * HH + h]);
    logits[i] = a;
    atomicAdd(&den[d * HH + h], a);
}

// -------------- agg[dst] += (a/den) * v[src] --------------------------------
__global__ void scatter_kernel(const float* __restrict__ a,
                               const float* __restrict__ den,
                               const float* __restrict__ vn,
                               const int* __restrict__ src,
                               const int* __restrict__ dst,
                               float* __restrict__ agg) {
    int e = (blockIdx.x * blockDim.x + threadIdx.x) >> 5;
    int lane = threadIdx.x & 31;
    if (e >= EE) return;
    int s = src[e], d = dst[e];
    float al[HH];
#pragma unroll
    for (int h = 0; h < HH; h++)
        al[h] = a[(size_t)e * HH + h] / (den[(size_t)d * HH + h] + 1e-12f);
    const float* vrow = vn + (size_t)s * DDIM;
    float* arow = agg + (size_t)d * DDIM;
#pragma unroll
    for (int t = 0; t < 15; t++) {
        int dd = t * 32 + lane;
        int h = dd / DHH;
        atomicAdd(&arow[dd], al[h] * vrow[dd]);
    }
}

// -------------- tiled fp32 SGEMM: C = act(alpha * A(M,K) @ B(K,N)) ----------
#define BM 128
#define BN 64
#define BK 16
__global__ __launch_bounds__(128) void sgemm_kernel(
    const float* __restrict__ A, const float* __restrict__ B,
    float* __restrict__ C, int M, int Ncol, int K, float alpha, int act) {
    __shared__ float As[BK][BM + 4];  // padded, 16B-aligned rows
    __shared__ float Bs[BK][BN];
    int tid = threadIdx.x;             // 128 threads
    int tcol = tid & 7;                // 8 col groups x 8
    int trow = tid >> 3;               // 16 row groups x 8
    int rowBase = blockIdx.y * BM;
    int colBase = blockIdx.x * BN;
    float acc[8][8];
#pragma unroll
    for (int i = 0; i < 8; i++)
#pragma unroll
        for (int j = 0; j < 8; j++) acc[i][j] = 0.f;

    for (int kb = 0; kb < K; kb += BK) {
        // A tile: BM x BK (row-major in gmem) -> As[k][m]
#pragma unroll
        for (int i = tid; i < BM * BK; i += 128) {
            int r = i >> 4, c = i & 15;
            int gr = rowBase + r;
            As[c][r] = (gr < M) ? A[(size_t)gr * K + kb + c] : 0.f;
        }
        // B tile: BK x BN
#pragma unroll
        for (int i = tid; i < BK * BN; i += 128) {
            int r = i >> 6, c = i & 63;
            int gc = colBase + c;
            Bs[r][c] = (gc < Ncol) ? B[(size_t)(kb + r) * Ncol + gc] : 0.f;
        }
        __syncthreads();
#pragma unroll
        for (int k = 0; k < BK; k++) {
            float ra[8], rb[8];
            float4 a0 = *(const float4*)&As[k][trow * 8];
            float4 a1 = *(const float4*)&As[k][trow * 8 + 4];
            float4 b0 = *(const float4*)&Bs[k][tcol * 8];
            float4 b1 = *(const float4*)&Bs[k][tcol * 8 + 4];
            ra[0] = a0.x; ra[1] = a0.y; ra[2] = a0.z; ra[3] = a0.w;
            ra[4] = a1.x; ra[5] = a1.y; ra[6] = a1.z; ra[7] = a1.w;
            rb[0] = b0.x; rb[1] = b0.y; rb[2] = b0.z; rb[3] = b0.w;
            rb[4] = b1.x; rb[5] = b1.y; rb[6] = b1.z; rb[7] = b1.w;
#pragma unroll
            for (int i = 0; i < 8; i++)
#pragma unroll
                for (int j = 0; j < 8; j++) acc[i][j] += ra[i] * rb[j];
        }
        __syncthreads();
    }
#pragma unroll
    for (int i = 0; i < 8; i++) {
        int gr = rowBase + trow * 8 + i;
        if (gr >= M) continue;
#pragma unroll
        for (int j = 0; j < 8; j++) {
            int gc = colBase + tcol * 8 + j;
            if (gc >= Ncol) continue;
            float v = acc[i][j] * alpha;
            if (act) v = siluf(v);
            C[(size_t)gr * Ncol + gc] = v;
        }
    }
}

// -------------- x = LayerNorm(x + y), row length 480 ------------------------
__global__ void ln_residual_kernel(float* __restrict__ x,
                                   const float* __restrict__ y) {
    int n = blockIdx.x;
    int tid = threadIdx.x;  // 128
    size_t base = (size_t)n * DDIM;
    float v[4];
    float s = 0.f;
#pragma unroll
    for (int t = 0; t < 4; t++) {
        int dd = tid + t * 128;
        v[t] = 0.f;
        if (dd < DDIM) {
            v[t] = x[base + dd] + y[base + dd];
            s += v[t];
        }
    }
    __shared__ float red[4];
    int wid = tid >> 5, lane = tid & 31;
    float ws = warpSum(s);
    if (lane == 0) red[wid] = ws;
    __syncthreads();
    float mean = (red[0] + red[1] + red[2] + red[3]) * (1.0f / DDIM);
    float vs = 0.f;
#pragma unroll
    for (int t = 0; t < 4; t++) {
        int dd = tid + t * 128;
        if (dd < DDIM) {
            float d0 = v[t] - mean;
            vs += d0 * d0;
        }
    }
    __syncthreads();
    float wv = warpSum(vs);
    if (lane == 0) red[wid] = wv;
    __syncthreads();
    float var = (red[0] + red[1] + red[2] + red[3]) * (1.0f / DDIM);
    float rstd = rsqrtf(var + 1e-5f);
#pragma unroll
    for (int t = 0; t < 4; t++) {
        int dd = tid + t * 128;
        if (dd < DDIM) x[base + dd] = (v[t] - mean) * rstd;
    }
}

// -------------- energy: out[batch[n]] += dot(hn[n], Wh2) / AVG_NODES --------
__global__ void zero_out_kernel(float* __restrict__ out) {
    int i = threadIdx.x;
    if (i < GGG) out[i] = 0.f;
}

__global__ void energy_kernel(const float* __restrict__ hn,
                              const float* __restrict__ Wh2,
                              const int* __restrict__ batch,
                              float* __restrict__ out) {
    int n = (blockIdx.x * blockDim.x + threadIdx.x) >> 5;
    int lane = threadIdx.x & 31;
    if (n >= NN) return;
    float p = 0.f;
#pragma unroll
    for (int t = 0; t < 15; t++) {
        int dd = t * 32 + lane;
        p += hn[(size_t)n * DDIM + dd] * Wh2[dd];
    }
    p = warpSum(p);
    if (lane == 0) atomicAdd(&out[batch[n]], p * (1.0f / AVG_NODES_F));
}

// ------------------------- host orchestration -------------------------------
static void launch_gemm(const float* A, const float* B, float* C,
                        int M, int Ncol, int K, float alpha, int act) {
    dim3 grid((Ncol + BN - 1) / BN, (M + BM - 1) / BM);
    sgemm_kernel<<<grid, 128>>>(A, B, C, M, Ncol, K, alpha, act);
}

extern "C" void kernel_launch(void* const* d_in, const int* in_sizes, int n_in,
                              void* d_out, int out_size) {
    // ---- resolve input ordering (setup-dict order vs signature order) ----
    const float *pos, *atom_table, *Wdeg, *Wd1, *Wd2, *Wd3, *Wq, *Wk, *Wv,
        *Wsh, *W1, *W2, *W3, *Wo, *Wf1, *Wf2, *Wh1, *Wh2;
    const int *node_atom, *edge_src, *edge_dst, *batch;

    if (in_sizes[1] == NN) {
        // dict order: pos, node_atom, edge_src, edge_dst, batch, atom_table,
        // Wdeg, Wd1, Wd2, Wd3, Wq, Wk, Wv, Wsh, W1, W2, W3, Wo, Wf1, Wf2, Wh1, Wh2
        pos = (const float*)d_in[0];
        node_atom = (const int*)d_in[1];
        edge_src = (const int*)d_in[2];
        edge_dst = (const int*)d_in[3];
        batch = (const int*)d_in[4];
        atom_table = (const float*)d_in[5];
        Wdeg = (const float*)d_in[6];
        Wd1 = (const float*)d_in[7];
        Wd2 = (const float*)d_in[8];
        Wd3 = (const float*)d_in[9];
        Wq = (const float*)d_in[10];
        Wk = (const float*)d_in[11];
        Wv = (const float*)d_in[12];
        Wsh = (const float*)d_in[13];
        W1 = (const float*)d_in[14];
        W2 = (const float*)d_in[15];
        W3 = (const float*)d_in[16];
        Wo = (const float*)d_in[17];
        Wf1 = (const float*)d_in[18];
        Wf2 = (const float*)d_in[19];
        Wh1 = (const float*)d_in[20];
        Wh2 = (const float*)d_in[21];
    } else {
        // signature order
        pos = (const float*)d_in[0];
        atom_table = (const float*)d_in[1];
        Wdeg = (const float*)d_in[2];
        Wd1 = (const float*)d_in[3];
        Wd2 = (const float*)d_in[4];
        Wd3 = (const float*)d_in[5];
        Wq = (const float*)d_in[6];
        Wk = (const float*)d_in[7];
        Wv = (const float*)d_in[8];
        Wsh = (const float*)d_in[9];
        W1 = (const float*)d_in[10];
        W2 = (const float*)d_in[11];
        W3 = (const float*)d_in[12];
        Wo = (const float*)d_in[13];
        Wf1 = (const float*)d_in[14];
        Wf2 = (const float*)d_in[15];
        Wh1 = (const float*)d_in[16];
        Wh2 = (const float*)d_in[17];
        node_atom = (const int*)d_in[18];
        edge_src = (const int*)d_in[19];
        edge_dst = (const int*)d_in[20];
        batch = (const int*)d_in[21];
    }

    float* buf = nullptr;
    cudaGetSymbolAddress((void**)&buf, g_buf);
    float* sh = buf + O_SH;
    float* rbf = buf + O_RBF;
    float* g0 = buf + O_G0;
    float* gate = buf + O_GATE;
    float* x = buf + O_X;
    float* qn = buf + O_QN;
    float* kn = buf + O_KN;
    float* vn = buf + O_VN;
    float* agg = buf + O_AGG;
    float* tmp = buf + O_TMP;
    float* hn = buf + O_HN;
    float* hid = buf + O_HID;
    float* logits = buf + O_LOG;
    float* mbuf = buf + O_M;
    float* den = buf + O_DEN;
    float* out = (float*)d_out;

    const float invAvgDeg = (float)(1.0 / sqrt((double)AVG_DEG_F));

    const int warpBlocks = (EE * 32 + 255) / 256;           // warp-per-edge grids
    const int ndBlocks = (NN * DDIM + 255) / 256;

    // ---- precompute (independent of x) ----
    edge_geom_kernel<<<warpBlocks, 256>>>(pos, edge_src, edge_dst, sh, rbf);
    edge_mlp_kernel<<<warpBlocks, 256>>>(rbf, Wd1, Wd2, Wd3, g0, 1);
    for (int l = 0; l < LLAY; l++) {
        edge_mlp_kernel<<<warpBlocks, 256>>>(rbf, W1 + (size_t)l * 128 * 64,
                                             W2 + (size_t)l * 64 * 64,
                                             W3 + (size_t)l * 64 * HH,
                                             gate + (size_t)l * EE * HH, HH);
    }

    // ---- node features ----
    embed_kernel<<<ndBlocks, 256>>>(atom_table, node_atom, x);
    deg_kernel<<<warpBlocks, 256>>>(sh, Wdeg, g0, edge_dst, x, invAvgDeg);

    // ---- transformer layers ----
    for (int l = 0; l < LLAY; l++) {
        const float* Wq_l = Wq + (size_t)l * DDIM * DDIM;
        const float* Wk_l = Wk + (size_t)l * DDIM * DDIM;
        const float* Wv_l = Wv + (size_t)l * DDIM * DDIM;
        const float* Wo_l = Wo + (size_t)l * DDIM * DDIM;
        const float* Wsh_l = Wsh + (size_t)l * SHN * DDIM;
        const float* Wf1_l = Wf1 + (size_t)l * DDIM * 2 * DDIM;
        const float* Wf2_l = Wf2 + (size_t)l * 2 * DDIM * DDIM;
        const float* gate_l = gate + (size_t)l * EE * HH;

        launch_gemm(x, Wq_l, qn, NN, DDIM, DDIM, 1.0f, 0);
        launch_gemm(x, Wk_l, kn, NN, DDIM, DDIM, 1.0f, 0);
        launch_gemm(x, Wv_l, vn, NN, DDIM, DDIM, 1.0f, 0);

        init_layer_kernel<<<ndBlocks, 256>>>(agg, mbuf, den);
        logits_kernel<<<warpBlocks, 256>>>(qn, kn, sh, Wsh_l, gate_l,
                                           edge_src, edge_dst, logits, mbuf);
        expden_kernel<<<(EE * HH + 255) / 256, 256>>>(logits, mbuf, den, edge_dst);
        scatter_kernel<<<warpBlocks, 256>>>(logits, den, vn, edge_src, edge_dst, agg);

        launch_gemm(agg, Wo_l, tmp, NN, DDIM, DDIM, invAvgDeg, 0);
        ln_residual_kernel<<<NN, 128>>>(x, tmp);

        launch_gemm(x, Wf1_l, hid, NN, 2 * DDIM, DDIM, 1.0f, 1);   // silu fused
        launch_gemm(hid, Wf2_l, tmp, NN, DDIM, 2 * DDIM, 1.0f, 0);
        ln_residual_kernel<<<NN, 128>>>(x, tmp);
    }

    // ---- readout ----
    launch_gemm(x, Wh1, hn, NN, DDIM, DDIM, 1.0f, 1);  // silu fused
    zero_out_kernel<<<1, 64>>>(out);
    energy_kernel<<<(NN * 32 + 255) / 256, 256>>>(hn, Wh2, batch, out);
}

// round 2
// speedup vs baseline: 1.3450x; 1.3450x over previous
#include <cuda_runtime.h>
#include <math.h>
#include <stdint.h>

// ---------------- problem constants ----------------
#define NN   10000
#define EE   160000
#define GGG  64
#define DDIM 480
#define HH   4
#define LLAY 6
#define DHH  120
#define NBB  128
#define SHN  9

static const float AVG_DEG_F   = 15.57930850982666f;
static const float AVG_NODES_F = 18.03065905448718f;

// ---------------- scratch buffer (static device memory; no runtime alloc) ----
constexpr size_t SZ_SH   = (size_t)EE * SHN;
constexpr size_t SZ_RBF  = (size_t)EE * NBB;
constexpr size_t SZ_G0   = (size_t)EE;
constexpr size_t SZ_GATE = (size_t)LLAY * EE * HH;
constexpr size_t SZ_ND   = (size_t)NN * DDIM;
constexpr size_t SZ_HID  = (size_t)NN * 2 * DDIM;
constexpr size_t SZ_LOG  = (size_t)EE * HH;
constexpr size_t SZ_NH   = (size_t)NN * HH;
constexpr size_t SZ_EH   = (size_t)EE * 64;

constexpr size_t O_SH   = 0;
constexpr size_t O_RBF  = O_SH   + SZ_SH;
constexpr size_t O_G0   = O_RBF  + SZ_RBF;
constexpr size_t O_GATE = O_G0   + SZ_G0;
constexpr size_t O_X    = O_GATE + SZ_GATE;
constexpr size_t O_QN   = O_X    + SZ_ND;
constexpr size_t O_KN   = O_QN   + SZ_ND;
constexpr size_t O_VN   = O_KN   + SZ_ND;
constexpr size_t O_AGG  = O_VN   + SZ_ND;
constexpr size_t O_TMP  = O_AGG  + SZ_ND;
constexpr size_t O_HN   = O_TMP  + SZ_ND;
constexpr size_t O_HID  = O_HN   + SZ_ND;
constexpr size_t O_LOG  = O_HID  + SZ_HID;
constexpr size_t O_M    = O_LOG  + SZ_LOG;
constexpr size_t O_DEN  = O_M    + SZ_NH;
constexpr size_t O_EH1  = O_DEN  + SZ_NH;
constexpr size_t O_EH2  = O_EH1  + SZ_EH;
constexpr size_t TOTAL_F = O_EH2 + SZ_EH;

__device__ float g_buf[TOTAL_F];

// ---------------- helpers ----------------
__device__ __forceinline__ float warpSum(float v) {
#pragma unroll
    for (int o = 16; o; o >>= 1) v += __shfl_down_sync(0xffffffffu, v, o);
    return v;
}

__device__ __forceinline__ float siluf(float x) {
    return x / (1.0f + expf(-x));
}

__device__ __forceinline__ void atomicMaxFloat(float* addr, float val) {
    int old = __float_as_int(*addr);
    while (__int_as_float(old) < val) {
        int prev = atomicCAS((int*)addr, old, __float_as_int(val));
        if (prev == old) break;
        old = prev;
    }
}

__device__ __forceinline__ uint32_t f2tf32(float v) {
    uint32_t r;
    asm("cvt.rna.tf32.f32 %0, %1;" : "=r"(r) : "f"(v));
    return r;
}

__device__ __forceinline__ void mma_tf32(float& c0, float& c1, float& c2, float& c3,
                                         uint32_t a0, uint32_t a1, uint32_t a2, uint32_t a3,
                                         uint32_t b0, uint32_t b1) {
    asm volatile(
        "mma.sync.aligned.m16n8k8.row.col.f32.tf32.tf32.f32 "
        "{%0,%1,%2,%3}, {%4,%5,%6,%7}, {%8,%9}, {%0,%1,%2,%3};\n"
        : "+f"(c0), "+f"(c1), "+f"(c2), "+f"(c3)
        : "r"(a0), "r"(a1), "r"(a2), "r"(a3), "r"(b0), "r"(b1));
}

// ---------------- edge geometry: sh (E,9) + rbf (E,128) -------------------
__global__ void edge_geom_kernel(const float* __restrict__ pos,
                                 const int* __restrict__ src,
                                 const int* __restrict__ dst,
                                 float* __restrict__ sh,
                                 float* __restrict__ rbf) {
    int e = (blockIdx.x * blockDim.x + threadIdx.x) >> 5;
    int lane = threadIdx.x & 31;
    if (e >= EE) return;
    int s = src[e], d = dst[e];
    float vx = pos[s * 3 + 0] - pos[d * 3 + 0];
    float vy = pos[s * 3 + 1] - pos[d * 3 + 1];
    float vz = pos[s * 3 + 2] - pos[d * 3 + 2];
    float r = sqrtf(vx * vx + vy * vy + vz * vz);
    float rr = r + 1e-12f;
    float x = vx / rr, y = vy / rr, z = vz / rr;
    if (lane == 0) {
        const float s3 = 1.7320508075688772f;   // sqrt(3)
        const float s5 = 2.23606797749979f;     // sqrt(5)
        const float s15 = 3.872983346207417f;   // sqrt(15)
        float* o = sh + (size_t)e * SHN;
        o[0] = 1.0f;
        o[1] = s3 * x;
        o[2] = s3 * y;
        o[3] = s3 * z;
        o[4] = s15 * x * y;
        o[5] = s15 * y * z;
        o[6] = 0.5f * s5 * (3.0f * z * z - 1.0f);
        o[7] = s15 * x * z;
        o[8] = 0.5f * s15 * (x * x - y * y);
    }
    const float width = 5.0f / 128.0f;      // CUTOFF / NB
    const float cstep = 5.0f / 127.0f;      // linspace(0, CUTOFF, NB) step
#pragma unroll
    for (int t = 0; t < 4; t++) {
        int i = t * 32 + lane;
        float c = cstep * (float)i;
        float u = (r - c) / width;
        rbf[(size_t)e * NBB + i] = expf(-u * u);
    }
}

// ---------------- tf32x3 tensor-core GEMM ----------------------------------
// C(M,N) = act(alpha * A(M,K) @ B(K,N)); K % 16 == 0, N % 4 == 0.
#define BM 128
#define BN 64
#define BK 16
#define ASTR 136   // BM + 8 pad -> conflict-free frag loads
#define BSTR 72    // BN + 8 pad

__global__ __launch_bounds__(256) void gemm_tf32_kernel(
    const float* __restrict__ A, const float* __restrict__ B,
    float* __restrict__ C, int M, int Ncol, int K, float alpha, int act) {
    __shared__ float As_hi[BK][ASTR];
    __shared__ float As_lo[BK][ASTR];
    __shared__ float Bs_hi[BK][BSTR];
    __shared__ float Bs_lo[BK][BSTR];

    const int tid = threadIdx.x;
    const int lane = tid & 31;
    const int w = tid >> 5;       // 8 warps
    const int warpM = w & 3;      // 4 M-warps (32 rows each)
    const int warpN = w >> 2;     // 2 N-warps (32 cols each)
    const int gid = lane >> 2;    // 0..7
    const int tig = lane & 3;     // 0..3

    const int rowBase = blockIdx.y * BM;
    const int colBase = blockIdx.x * BN;

    float c[2][4][4];
#pragma unroll
    for (int mt = 0; mt < 2; mt++)
#pragma unroll
        for (int nt = 0; nt < 4; nt++)
#pragma unroll
            for (int i = 0; i < 4; i++) c[mt][nt][i] = 0.f;

    // loader indices
    const int ar = tid >> 2;          // 0..63
    const int ac = (tid & 3) * 4;     // 0,4,8,12
    const int bk = tid >> 4;          // 0..15
    const int bn = (tid & 15) * 4;    // 0..60

    for (int kb = 0; kb < K; kb += BK) {
        // ---- load A tile (BM x BK), transpose into As[k][m], split hi/lo ----
#pragma unroll
        for (int half = 0; half < 2; half++) {
            int rr = ar + half * 64;
            int gr = rowBase + rr;
            float4 av = make_float4(0.f, 0.f, 0.f, 0.f);
            if (gr < M) av = *(const float4*)&A[(size_t)gr * K + kb + ac];
            float vv[4] = {av.x, av.y, av.z, av.w};
#pragma unroll
            for (int j = 0; j < 4; j++) {
                float v = vv[j];
                uint32_t hb = f2tf32(v);
                float hf = __uint_as_float(hb);
                float lf = v - hf;
                As_hi[ac + j][rr] = hf;
                As_lo[ac + j][rr] = __uint_as_float(f2tf32(lf));
            }
        }
        // ---- load B tile (BK x BN) into Bs[k][n], split hi/lo ----
        {
            int gc = colBase + bn;
            float4 bv = make_float4(0.f, 0.f, 0.f, 0.f);
            if (gc + 3 < Ncol) bv = *(const float4*)&B[(size_t)(kb + bk) * Ncol + gc];
            float vv[4] = {bv.x, bv.y, bv.z, bv.w};
#pragma unroll
            for (int j = 0; j < 4; j++) {
                float v = vv[j];
                uint32_t hb = f2tf32(v);
                float hf = __uint_as_float(hb);
                float lf = v - hf;
                Bs_hi[bk][bn + j] = hf;
                Bs_lo[bk][bn + j] = __uint_as_float(f2tf32(lf));
            }
        }
        __syncthreads();

#pragma unroll
        for (int kk = 0; kk < 2; kk++) {
            const int k0 = kk * 8;
            uint32_t ah[2][4], al[2][4], bh[4][2], bl[4][2];
#pragma unroll
            for (int mt = 0; mt < 2; mt++) {
                int m = warpM * 32 + mt * 16 + gid;
                ah[mt][0] = __float_as_uint(As_hi[k0 + tig][m]);
                ah[mt][1] = __float_as_uint(As_hi[k0 + tig][m + 8]);
                ah[mt][2] = __float_as_uint(As_hi[k0 + tig + 4][m]);
                ah[mt][3] = __float_as_uint(As_hi[k0 + tig + 4][m + 8]);
                al[mt][0] = __float_as_uint(As_lo[k0 + tig][m]);
                al[mt][1] = __float_as_uint(As_lo[k0 + tig][m + 8]);
                al[mt][2] = __float_as_uint(As_lo[k0 + tig + 4][m]);
                al[mt][3] = __float_as_uint(As_lo[k0 + tig + 4][m + 8]);
            }
#pragma unroll
            for (int nt = 0; nt < 4; nt++) {
                int n = warpN * 32 + nt * 8 + gid;
                bh[nt][0] = __float_as_uint(Bs_hi[k0 + tig][n]);
                bh[nt][1] = __float_as_uint(Bs_hi[k0 + tig + 4][n]);
                bl[nt][0] = __float_as_uint(Bs_lo[k0 + tig][n]);
                bl[nt][1] = __float_as_uint(Bs_lo[k0 + tig + 4][n]);
            }
#pragma unroll
            for (int mt = 0; mt < 2; mt++)
#pragma unroll
                for (int nt = 0; nt < 4; nt++) {
                    mma_tf32(c[mt][nt][0], c[mt][nt][1], c[mt][nt][2], c[mt][nt][3],
                             ah[mt][0], ah[mt][1], ah[mt][2], ah[mt][3],
                             bh[nt][0], bh[nt][1]);
                    mma_tf32(c[mt][nt][0], c[mt][nt][1], c[mt][nt][2], c[mt][nt][3],
                             ah[mt][0], ah[mt][1], ah[mt][2], ah[mt][3],
                             bl[nt][0], bl[nt][1]);
                    mma_tf32(c[mt][nt][0], c[mt][nt][1], c[mt][nt][2], c[mt][nt][3],
                             al[mt][0], al[mt][1], al[mt][2], al[mt][3],
                             bh[nt][0], bh[nt][1]);
                }
        }
        __syncthreads();
    }

    // ---- epilogue ----
#pragma unroll
    for (int mt = 0; mt < 2; mt++) {
#pragma unroll
        for (int nt = 0; nt < 4; nt++) {
            int gr0 = rowBase + warpM * 32 + mt * 16 + gid;
            int gc0 = colBase + warpN * 32 + nt * 8 + 2 * tig;
#pragma unroll
            for (int i = 0; i < 4; i++) {
                int gr = gr0 + (i >> 1) * 8;
                int gc = gc0 + (i & 1);
                if (gr < M && gc < Ncol) {
                    float v = c[mt][nt][i] * alpha;
                    if (act) v = siluf(v);
                    C[(size_t)gr * Ncol + gc] = v;
                }
            }
        }
    }
}

// -------------- MLP third layer: out(E,OD) = H2(E,64) @ W3(64,OD) ----------
__global__ void mlp3_kernel(const float* __restrict__ H2,
                            const float* __restrict__ W3,
                            float* __restrict__ out, int OD) {
    int e = (blockIdx.x * blockDim.x + threadIdx.x) >> 5;
    int lane = threadIdx.x & 31;
    if (e >= EE) return;
    float v0 = H2[(size_t)e * 64 + lane];
    float v1 = H2[(size_t)e * 64 + lane + 32];
    for (int o = 0; o < OD; o++) {
        float p = v0 * W3[lane * OD + o] + v1 * W3[(lane + 32) * OD + o];
        p = warpSum(p);
        if (lane == 0) out[(size_t)e * OD + o] = p;
    }
}

// -------------- x = atom_table[node_atom] ----------------------------------
__global__ void embed_kernel(const float* __restrict__ atom_table,
                             const int* __restrict__ node_atom,
                             float* __restrict__ x) {
    int i = blockIdx.x * blockDim.x + threadIdx.x;
    if (i >= NN * DDIM) return;
    int n = i / DDIM, dd = i - n * DDIM;
    x[i] = atom_table[node_atom[n] * DDIM + dd];
}

// -------------- x += (sh@Wdeg)*g0 / sqrt(AVG_DEG), scattered to dst --------
__global__ void deg_kernel(const float* __restrict__ sh,
                           const float* __restrict__ Wdeg,  // (9,480)
                           const float* __restrict__ g0,
                           const int* __restrict__ dst,
                           float* __restrict__ x, float scale) {
    int e = (blockIdx.x * blockDim.x + threadIdx.x) >> 5;
    int lane = threadIdx.x & 31;
    if (e >= EE) return;
    int d = dst[e];
    float shreg[SHN];
#pragma unroll
    for (int i = 0; i < SHN; i++) shreg[i] = sh[(size_t)e * SHN + i];
    float g = g0[e] * scale;
#pragma unroll
    for (int t = 0; t < 15; t++) {
        int dd = t * 32 + lane;
        float val = 0.f;
#pragma unroll
        for (int si = 0; si < SHN; si++) val += shreg[si] * Wdeg[si * DDIM + dd];
        atomicAdd(&x[(size_t)d * DDIM + dd], val * g);
    }
}

// -------------- per-layer init: agg=0, m=-inf, den=0 -----------------------
__global__ void init_layer_kernel(float* __restrict__ agg,
                                  float* __restrict__ m,
                                  float* __restrict__ den) {
    int i = blockIdx.x * blockDim.x + threadIdx.x;
    if (i < NN * DDIM) agg[i] = 0.f;
    if (i < NN * HH) {
        m[i] = __int_as_float(0xff800000);  // -inf
        den[i] = 0.f;
    }
}

// -------------- logits[e,h] = inv*gate * q[dst]·(k[src]+sh@Wsh) ------------
__global__ void logits_kernel(const float* __restrict__ qn,
                              const float* __restrict__ kn,
                              const float* __restrict__ sh,
                              const float* __restrict__ Wsh_l,  // (9,480)
                              const float* __restrict__ gate_l, // (E,4)
                              const int* __restrict__ src,
                              const int* __restrict__ dst,
                              float* __restrict__ logits,
                              float* __restrict__ m) {
    int e = (blockIdx.x * blockDim.x + threadIdx.x) >> 5;
    int lane = threadIdx.x & 31;
    if (e >= EE) return;
    int s = src[e], d = dst[e];
    float shreg[SHN];
#pragma unroll
    for (int i = 0; i < SHN; i++) shreg[i] = sh[(size_t)e * SHN + i];
    const float* qrow = qn + (size_t)d * DDIM;
    const float* krow = kn + (size_t)s * DDIM;
    const float inv = 0.09128709291752768f;  // 1/sqrt(120)
#pragma unroll
    for (int h = 0; h < HH; h++) {
        float acc = 0.f;
#pragma unroll
        for (int t = 0; t < 4; t++) {
            int j = t * 32 + lane;
            if (j < DHH) {
                int dd = h * DHH + j;
                float kv = krow[dd];
                float shk = 0.f;
#pragma unroll
                for (int si = 0; si < SHN; si++) shk += shreg[si] * Wsh_l[si * DDIM + dd];
                acc += qrow[dd] * (kv + shk);
            }
        }
        acc = warpSum(acc);
        if (lane == 0) {
            float lg = acc * inv * gate_l[(size_t)e * HH + h];
            logits[(size_t)e * HH + h] = lg;
            atomicMaxFloat(&m[(size_t)d * HH + h], lg);
        }
    }
}

// -------------- a = exp(logit - m[dst]); den[dst] += a ----------------------
__global__ void expden_kernel(float* __restrict__ logits,
                              const float* __restrict__ m,
                              float* __restrict__ den,
                              const int* __restrict__ dst) {
    int i = blockIdx.x * blockDim.x + threadIdx.x;
    if (i >= EE * HH) return;
    int e = i >> 2, h = i & 3;
    int d = dst[e];
    float a = expf(logits[i] - m[d * HH + h]);
    logits[i] = a;
    atomicAdd(&den[d * HH + h], a);
}

// -------------- agg[dst] += (a/den) * v[src] --------------------------------
__global__ void scatter_kernel(const float* __restrict__ a,
                               const float* __restrict__ den,
                               const float* __restrict__ vn,
                               const int* __restrict__ src,
                               const int* __restrict__ dst,
                               float* __restrict__ agg) {
    int e = (blockIdx.x * blockDim.x + threadIdx.x) >> 5;
    int lane = threadIdx.x & 31;
    if (e >= EE) return;
    int s = src[e], d = dst[e];
    float al[HH];
#pragma unroll
    for (int h = 0; h < HH; h++)
        al[h] = a[(size_t)e * HH + h] / (den[(size_t)d * HH + h] + 1e-12f);
    const float* vrow = vn + (size_t)s * DDIM;
    float* arow = agg + (size_t)d * DDIM;
#pragma unroll
    for (int t = 0; t < 15; t++) {
        int dd = t * 32 + lane;
        int h = dd / DHH;
        atomicAdd(&arow[dd], al[h] * vrow[dd]);
    }
}

// -------------- x = LayerNorm(x + y), row length 480 ------------------------
__global__ void ln_residual_kernel(float* __restrict__ x,
                                   const float* __restrict__ y) {
    int n = blockIdx.x;
    int tid = threadIdx.x;  // 128
    size_t base = (size_t)n * DDIM;
    float v[4];
    float s = 0.f;
#pragma unroll
    for (int t = 0; t < 4; t++) {
        int dd = tid + t * 128;
        v[t] = 0.f;
        if (dd < DDIM) {
            v[t] = x[base + dd] + y[base + dd];
            s += v[t];
        }
    }
    __shared__ float red[4];
    int wid = tid >> 5, lane = tid & 31;
    float ws = warpSum(s);
    if (lane == 0) red[wid] = ws;
    __syncthreads();
    float mean = (red[0] + red[1] + red[2] + red[3]) * (1.0f / DDIM);
    float vs = 0.f;
#pragma unroll
    for (int t = 0; t < 4; t++) {
        int dd = tid + t * 128;
        if (dd < DDIM) {
            float d0 = v[t] - mean;
            vs += d0 * d0;
        }
    }
    __syncthreads();
    float wv = warpSum(vs);
    if (lane == 0) red[wid] = wv;
    __syncthreads();
    float var = (red[0] + red[1] + red[2] + red[3]) * (1.0f / DDIM);
    float rstd = rsqrtf(var + 1e-5f);
#pragma unroll
    for (int t = 0; t < 4; t++) {
        int dd = tid + t * 128;
        if (dd < DDIM) x[base + dd] = (v[t] - mean) * rstd;
    }
}

// -------------- energy ------------------------------------------------------
__global__ void zero_out_kernel(float* __restrict__ out) {
    int i = threadIdx.x;
    if (i < GGG) out[i] = 0.f;
}

__global__ void energy_kernel(const float* __restrict__ hn,
                              const float* __restrict__ Wh2,
                              const int* __restrict__ batch,
                              float* __restrict__ out) {
    int n = (blockIdx.x * blockDim.x + threadIdx.x) >> 5;
    int lane = threadIdx.x & 31;
    if (n >= NN) return;
    float p = 0.f;
#pragma unroll
    for (int t = 0; t < 15; t++) {
        int dd = t * 32 + lane;
        p += hn[(size_t)n * DDIM + dd] * Wh2[dd];
    }
    p = warpSum(p);
    if (lane == 0) atomicAdd(&out[batch[n]], p * (1.0f / AVG_NODES_F));
}

// ------------------------- host orchestration -------------------------------
static void launch_gemm(const float* A, const float* B, float* C,
                        int M, int Ncol, int K, float alpha, int act) {
    dim3 grid((Ncol + BN - 1) / BN, (M + BM - 1) / BM);
    gemm_tf32_kernel<<<grid, 256>>>(A, B, C, M, Ncol, K, alpha, act);
}

extern "C" void kernel_launch(void* const* d_in, const int* in_sizes, int n_in,
                              void* d_out, int out_size) {
    // ---- resolve input ordering (setup-dict order vs signature order) ----
    const float *pos, *atom_table, *Wdeg, *Wd1, *Wd2, *Wd3, *Wq, *Wk, *Wv,
        *Wsh, *W1, *W2, *W3, *Wo, *Wf1, *Wf2, *Wh1, *Wh2;
    const int *node_atom, *edge_src, *edge_dst, *batch;

    if (in_sizes[1] == NN) {
        pos = (const float*)d_in[0];
        node_atom = (const int*)d_in[1];
        edge_src = (const int*)d_in[2];
        edge_dst = (const int*)d_in[3];
        batch = (const int*)d_in[4];
        atom_table = (const float*)d_in[5];
        Wdeg = (const float*)d_in[6];
        Wd1 = (const float*)d_in[7];
        Wd2 = (const float*)d_in[8];
        Wd3 = (const float*)d_in[9];
        Wq = (const float*)d_in[10];
        Wk = (const float*)d_in[11];
        Wv = (const float*)d_in[12];
        Wsh = (const float*)d_in[13];
        W1 = (const float*)d_in[14];
        W2 = (const float*)d_in[15];
        W3 = (const float*)d_in[16];
        Wo = (const float*)d_in[17];
        Wf1 = (const float*)d_in[18];
        Wf2 = (const float*)d_in[19];
        Wh1 = (const float*)d_in[20];
        Wh2 = (const float*)d_in[21];
    } else {
        pos = (const float*)d_in[0];
        atom_table = (const float*)d_in[1];
        Wdeg = (const float*)d_in[2];
        Wd1 = (const float*)d_in[3];
        Wd2 = (const float*)d_in[4];
        Wd3 = (const float*)d_in[5];
        Wq = (const float*)d_in[6];
        Wk = (const float*)d_in[7];
        Wv = (const float*)d_in[8];
        Wsh = (const float*)d_in[9];
        W1 = (const float*)d_in[10];
        W2 = (const float*)d_in[11];
        W3 = (const float*)d_in[12];
        Wo = (const float*)d_in[13];
        Wf1 = (const float*)d_in[14];
        Wf2 = (const float*)d_in[15];
        Wh1 = (const float*)d_in[16];
        Wh2 = (const float*)d_in[17];
        node_atom = (const int*)d_in[18];
        edge_src = (const int*)d_in[19];
        edge_dst = (const int*)d_in[20];
        batch = (const int*)d_in[21];
    }

    float* buf = nullptr;
    cudaGetSymbolAddress((void**)&buf, g_buf);
    float* sh = buf + O_SH;
    float* rbf = buf + O_RBF;
    float* g0 = buf + O_G0;
    float* gate = buf + O_GATE;
    float* x = buf + O_X;
    float* qn = buf + O_QN;
    float* kn = buf + O_KN;
    float* vn = buf + O_VN;
    float* agg = buf + O_AGG;
    float* tmp = buf + O_TMP;
    float* hn = buf + O_HN;
    float* hid = buf + O_HID;
    float* logits = buf + O_LOG;
    float* mbuf = buf + O_M;
    float* den = buf + O_DEN;
    float* eh1 = buf + O_EH1;
    float* eh2 = buf + O_EH2;
    float* out = (float*)d_out;

    const float invAvgDeg = (float)(1.0 / sqrt((double)AVG_DEG_F));

    const int warpBlocks = (EE * 32 + 255) / 256;           // warp-per-edge grids
    const int ndBlocks = (NN * DDIM + 255) / 256;

    // ---- precompute (independent of x) ----
    edge_geom_kernel<<<warpBlocks, 256>>>(pos, edge_src, edge_dst, sh, rbf);

    // g0 MLP via GEMMs
    launch_gemm(rbf, Wd1, eh1, EE, 64, NBB, 1.0f, 1);
    launch_gemm(eh1, Wd2, eh2, EE, 64, 64, 1.0f, 1);
    mlp3_kernel<<<warpBlocks, 256>>>(eh2, Wd3, g0, 1);

    // per-layer gate MLPs via GEMMs
    for (int l = 0; l < LLAY; l++) {
        launch_gemm(rbf, W1 + (size_t)l * 128 * 64, eh1, EE, 64, NBB, 1.0f, 1);
        launch_gemm(eh1, W2 + (size_t)l * 64 * 64, eh2, EE, 64, 64, 1.0f, 1);
        mlp3_kernel<<<warpBlocks, 256>>>(eh2, W3 + (size_t)l * 64 * HH,
                                         gate + (size_t)l * EE * HH, HH);
    }

    // ---- node features ----
    embed_kernel<<<ndBlocks, 256>>>(atom_table, node_atom, x);
    deg_kernel<<<warpBlocks, 256>>>(sh, Wdeg, g0, edge_dst, x, invAvgDeg);

    // ---- transformer layers ----
    for (int l = 0; l < LLAY; l++) {
        const float* Wq_l = Wq + (size_t)l * DDIM * DDIM;
        const float* Wk_l = Wk + (size_t)l * DDIM * DDIM;
        const float* Wv_l = Wv + (size_t)l * DDIM * DDIM;
        const float* Wo_l = Wo + (size_t)l * DDIM * DDIM;
        const float* Wsh_l = Wsh + (size_t)l * SHN * DDIM;
        const float* Wf1_l = Wf1 + (size_t)l * DDIM * 2 * DDIM;
        const float* Wf2_l = Wf2 + (size_t)l * 2 * DDIM * DDIM;
        const float* gate_l = gate + (size_t)l * EE * HH;

        launch_gemm(x, Wq_l, qn, NN, DDIM, DDIM, 1.0f, 0);
        launch_gemm(x, Wk_l, kn, NN, DDIM, DDIM, 1.0f, 0);
        launch_gemm(x, Wv_l, vn, NN, DDIM, DDIM, 1.0f, 0);

        init_layer_kernel<<<ndBlocks, 256>>>(agg, mbuf, den);
        logits_kernel<<<warpBlocks, 256>>>(qn, kn, sh, Wsh_l, gate_l,
                                           edge_src, edge_dst, logits, mbuf);
        expden_kernel<<<(EE * HH + 255) / 256, 256>>>(logits, mbuf, den, edge_dst);
        scatter_kernel<<<warpBlocks, 256>>>(logits, den, vn, edge_src, edge_dst, agg);

        launch_gemm(agg, Wo_l, tmp, NN, DDIM, DDIM, invAvgDeg, 0);
        ln_residual_kernel<<<NN, 128>>>(x, tmp);

        launch_gemm(x, Wf1_l, hid, NN, 2 * DDIM, DDIM, 1.0f, 1);   // silu fused
        launch_gemm(hid, Wf2_l, tmp, NN, DDIM, 2 * DDIM, 1.0f, 0);
        ln_residual_kernel<<<NN, 128>>>(x, tmp);
    }

    // ---- readout ----
    launch_gemm(x, Wh1, hn, NN, DDIM, DDIM, 1.0f, 1);  // silu fused
    zero_out_kernel<<<1, 64>>>(out);
    energy_kernel<<<(NN * 32 + 255) / 256, 256>>>(hn, Wh2, batch, out);
}

// round 3
// speedup vs baseline: 2.0972x; 1.5592x over previous
#include <cuda_runtime.h>
#include <cuda_bf16.h>
#include <math.h>
#include <stdint.h>

// ---------------- problem constants ----------------
#define NN   10000
#define EE   160000
#define GGG  64
#define DDIM 480
#define HH   4
#define LLAY 6
#define DHH  120
#define NBB  128
#define SHN  9

static const float AVG_DEG_F   = 15.57930850982666f;
static const float AVG_NODES_F = 18.03065905448718f;

// ---------------- scratch buffer (static device memory; no runtime alloc) ----
constexpr size_t SZ_SH   = (size_t)EE * SHN;
constexpr size_t SZ_RBF  = (size_t)EE * NBB;
constexpr size_t SZ_G0   = (size_t)EE;
constexpr size_t SZ_GATE = (size_t)LLAY * EE * HH;
constexpr size_t SZ_ND   = (size_t)NN * DDIM;
constexpr size_t SZ_HID  = (size_t)NN * 2 * DDIM;
constexpr size_t SZ_LOG  = (size_t)EE * HH;
constexpr size_t SZ_NH   = (size_t)NN * HH;
constexpr size_t SZ_EH   = (size_t)EE * 64;

constexpr size_t O_SH   = 0;
constexpr size_t O_RBF  = O_SH   + SZ_SH;
constexpr size_t O_G0   = O_RBF  + SZ_RBF;
constexpr size_t O_GATE = O_G0   + SZ_G0;
constexpr size_t O_X    = O_GATE + SZ_GATE;
constexpr size_t O_QN   = O_X    + SZ_ND;
constexpr size_t O_KN   = O_QN   + SZ_ND;
constexpr size_t O_VN   = O_KN   + SZ_ND;
constexpr size_t O_AGG  = O_VN   + SZ_ND;
constexpr size_t O_TMP  = O_AGG  + SZ_ND;
constexpr size_t O_HN   = O_TMP  + SZ_ND;
constexpr size_t O_HID  = O_HN   + SZ_ND;
constexpr size_t O_LOG  = O_HID  + SZ_HID;
constexpr size_t O_M    = O_LOG  + SZ_LOG;
constexpr size_t O_DEN  = O_M    + SZ_NH;
constexpr size_t O_EH1  = O_DEN  + SZ_NH;
constexpr size_t O_EH2  = O_EH1  + SZ_EH;
constexpr size_t TOTAL_F = O_EH2 + SZ_EH;

__device__ float g_buf[TOTAL_F];

// ---------------- helpers ----------------
__device__ __forceinline__ float warpSum(float v) {
#pragma unroll
    for (int o = 16; o; o >>= 1) v += __shfl_down_sync(0xffffffffu, v, o);
    return v;
}

__device__ __forceinline__ float siluf(float x) {
    return x / (1.0f + expf(-x));
}

__device__ __forceinline__ void atomicMaxFloat(float* addr, float val) {
    int old = __float_as_int(*addr);
    while (__int_as_float(old) < val) {
        int prev = atomicCAS((int*)addr, old, __float_as_int(val));
        if (prev == old) break;
        old = prev;
    }
}

// pack two floats into bf16x2 (hi parts) and residual bf16x2 (lo parts)
__device__ __forceinline__ void split_pack(float v0, float v1,
                                           uint32_t& uhi, uint32_t& ulo) {
    __nv_bfloat162 h;
    h.x = __float2bfloat16_rn(v0);
    h.y = __float2bfloat16_rn(v1);
    float r0 = v0 - __bfloat162float(h.x);
    float r1 = v1 - __bfloat162float(h.y);
    __nv_bfloat162 l;
    l.x = __float2bfloat16_rn(r0);
    l.y = __float2bfloat16_rn(r1);
    uhi = *reinterpret_cast<uint32_t*>(&h);
    ulo = *reinterpret_cast<uint32_t*>(&l);
}

__device__ __forceinline__ void mma_bf16(float& c0, float& c1, float& c2, float& c3,
                                         uint32_t a0, uint32_t a1, uint32_t a2, uint32_t a3,
                                         uint32_t b0, uint32_t b1) {
    asm volatile(
        "mma.sync.aligned.m16n8k16.row.col.f32.bf16.bf16.f32 "
        "{%0,%1,%2,%3}, {%4,%5,%6,%7}, {%8,%9}, {%0,%1,%2,%3};\n"
        : "+f"(c0), "+f"(c1), "+f"(c2), "+f"(c3)
        : "r"(a0), "r"(a1), "r"(a2), "r"(a3), "r"(b0), "r"(b1));
}

// ---------------- edge geometry: sh (E,9) + rbf (E,128) -------------------
__global__ void edge_geom_kernel(const float* __restrict__ pos,
                                 const int* __restrict__ src,
                                 const int* __restrict__ dst,
                                 float* __restrict__ sh,
                                 float* __restrict__ rbf) {
    int e = (blockIdx.x * blockDim.x + threadIdx.x) >> 5;
    int lane = threadIdx.x & 31;
    if (e >= EE) return;
    int s = src[e], d = dst[e];
    float vx = pos[s * 3 + 0] - pos[d * 3 + 0];
    float vy = pos[s * 3 + 1] - pos[d * 3 + 1];
    float vz = pos[s * 3 + 2] - pos[d * 3 + 2];
    float r = sqrtf(vx * vx + vy * vy + vz * vz);
    float rr = r + 1e-12f;
    float x = vx / rr, y = vy / rr, z = vz / rr;
    if (lane == 0) {
        const float s3 = 1.7320508075688772f;
        const float s5 = 2.23606797749979f;
        const float s15 = 3.872983346207417f;
        float* o = sh + (size_t)e * SHN;
        o[0] = 1.0f;
        o[1] = s3 * x;
        o[2] = s3 * y;
        o[3] = s3 * z;
        o[4] = s15 * x * y;
        o[5] = s15 * y * z;
        o[6] = 0.5f * s5 * (3.0f * z * z - 1.0f);
        o[7] = s15 * x * z;
        o[8] = 0.5f * s15 * (x * x - y * y);
    }
    const float width = 5.0f / 128.0f;
    const float cstep = 5.0f / 127.0f;
#pragma unroll
    for (int t = 0; t < 4; t++) {
        int i = t * 32 + lane;
        float c = cstep * (float)i;
        float u = (r - c) / width;
        rbf[(size_t)e * NBB + i] = expf(-u * u);
    }
}

// ---------------- bf16x3 tensor-core GEMM ----------------------------------
// C(M,N) = act(alpha * A(M,K) @ B(K,N)); K % 32 == 0, N % 4 == 0.
// Error-compensated: A = Ah + Al, B = Bh + Bl (bf16 splits);
// C ≈ Ah·Bh + Ah·Bl + Al·Bh  (fp32 accumulate)
#define BM 128
#define BN 64
#define BK 32
#define K2T (BK / 2)   // 16 packed-k rows
#define ASTR 136       // BM + 8 pad (uint32 elems)
#define BSTR 72        // BN + 8 pad

__global__ __launch_bounds__(256) void gemm_bf16x3_kernel(
    const float* __restrict__ A, const float* __restrict__ B,
    float* __restrict__ C, int M, int Ncol, int K, float alpha, int act) {
    __shared__ uint32_t As_hi[K2T][ASTR];
    __shared__ uint32_t As_lo[K2T][ASTR];
    __shared__ uint32_t Bs_hi[K2T][BSTR];
    __shared__ uint32_t Bs_lo[K2T][BSTR];

    const int tid = threadIdx.x;
    const int lane = tid & 31;
    const int w = tid >> 5;       // 8 warps
    const int warpM = w & 3;      // 4 M-warps (32 rows each)
    const int warpN = w >> 2;     // 2 N-warps (32 cols each)
    const int gid = lane >> 2;    // 0..7
    const int tig = lane & 3;     // 0..3

    const int rowBase = blockIdx.y * BM;
    const int colBase = blockIdx.x * BN;

    float c[2][4][4];
#pragma unroll
    for (int mt = 0; mt < 2; mt++)
#pragma unroll
        for (int nt = 0; nt < 4; nt++)
#pragma unroll
            for (int i = 0; i < 4; i++) c[mt][nt][i] = 0.f;

    // A loader: 128 rows x 32 k-cols; 256 threads, each float4 x 4 row-halves
    const int ar = tid >> 3;          // 0..31 (row group base)
    const int ac = (tid & 7) * 4;     // k offset 0,4,...,28
    // B loader: 32 k-rows x 64 n; 256 threads: k2 = tid>>4 (0..15), n4 = (tid&15)*4
    const int bk2 = tid >> 4;         // 0..15
    const int bn = (tid & 15) * 4;

    for (int kb = 0; kb < K; kb += BK) {
        // ---- A tile: read float4 (4 consecutive k), split hi/lo, pack k-pairs
#pragma unroll
        for (int half = 0; half < 4; half++) {
            int rr = ar + half * 32;
            int gr = rowBase + rr;
            float4 av = make_float4(0.f, 0.f, 0.f, 0.f);
            if (gr < M) av = *(const float4*)&A[(size_t)gr * K + kb + ac];
            uint32_t uh, ul;
            split_pack(av.x, av.y, uh, ul);
            As_hi[(ac >> 1) + 0][rr] = uh;
            As_lo[(ac >> 1) + 0][rr] = ul;
            split_pack(av.z, av.w, uh, ul);
            As_hi[(ac >> 1) + 1][rr] = uh;
            As_lo[(ac >> 1) + 1][rr] = ul;
        }
        // ---- B tile: read two k-rows (2*bk2, 2*bk2+1), pack pairs across k
        {
            int gc = colBase + bn;
            float4 b0 = make_float4(0.f, 0.f, 0.f, 0.f);
            float4 b1 = make_float4(0.f, 0.f, 0.f, 0.f);
            if (gc < Ncol) {
                b0 = *(const float4*)&B[(size_t)(kb + 2 * bk2) * Ncol + gc];
                b1 = *(const float4*)&B[(size_t)(kb + 2 * bk2 + 1) * Ncol + gc];
            }
            const float v0[4] = {b0.x, b0.y, b0.z, b0.w};
            const float v1[4] = {b1.x, b1.y, b1.z, b1.w};
#pragma unroll
            for (int j = 0; j < 4; j++) {
                uint32_t uh, ul;
                split_pack(v0[j], v1[j], uh, ul);  // low half = even k
                Bs_hi[bk2][bn + j] = uh;
                Bs_lo[bk2][bn + j] = ul;
            }
        }
        __syncthreads();

#pragma unroll
        for (int ks = 0; ks < 2; ks++) {       // two k16 steps
            const int k2b = ks * 8;
            uint32_t ah[2][4], al[2][4], bh[4][2], bl[4][2];
#pragma unroll
            for (int mt = 0; mt < 2; mt++) {
                int m = warpM * 32 + mt * 16 + gid;
                ah[mt][0] = As_hi[k2b + tig][m];
                ah[mt][1] = As_hi[k2b + tig][m + 8];
                ah[mt][2] = As_hi[k2b + tig + 4][m];
                ah[mt][3] = As_hi[k2b + tig + 4][m + 8];
                al[mt][0] = As_lo[k2b + tig][m];
                al[mt][1] = As_lo[k2b + tig][m + 8];
                al[mt][2] = As_lo[k2b + tig + 4][m];
                al[mt][3] = As_lo[k2b + tig + 4][m + 8];
            }
#pragma unroll
            for (int nt = 0; nt < 4; nt++) {
                int n = warpN * 32 + nt * 8 + gid;
                bh[nt][0] = Bs_hi[k2b + tig][n];
                bh[nt][1] = Bs_hi[k2b + tig + 4][n];
                bl[nt][0] = Bs_lo[k2b + tig][n];
                bl[nt][1] = Bs_lo[k2b + tig + 4][n];
            }
#pragma unroll
            for (int mt = 0; mt < 2; mt++)
#pragma unroll
                for (int nt = 0; nt < 4; nt++) {
                    mma_bf16(c[mt][nt][0], c[mt][nt][1], c[mt][nt][2], c[mt][nt][3],
                             ah[mt][0], ah[mt][1], ah[mt][2], ah[mt][3],
                             bh[nt][0], bh[nt][1]);
                    mma_bf16(c[mt][nt][0], c[mt][nt][1], c[mt][nt][2], c[mt][nt][3],
                             ah[mt][0], ah[mt][1], ah[mt][2], ah[mt][3],
                             bl[nt][0], bl[nt][1]);
                    mma_bf16(c[mt][nt][0], c[mt][nt][1], c[mt][nt][2], c[mt][nt][3],
                             al[mt][0], al[mt][1], al[mt][2], al[mt][3],
                             bh[nt][0], bh[nt][1]);
                }
        }
        __syncthreads();
    }

    // ---- epilogue ----
#pragma unroll
    for (int mt = 0; mt < 2; mt++) {
#pragma unroll
        for (int nt = 0; nt < 4; nt++) {
            int gr0 = rowBase + warpM * 32 + mt * 16 + gid;
            int gc0 = colBase + warpN * 32 + nt * 8 + 2 * tig;
#pragma unroll
            for (int i = 0; i < 4; i++) {
                int gr = gr0 + (i >> 1) * 8;
                int gc = gc0 + (i & 1);
                if (gr < M && gc < Ncol) {
                    float v = c[mt][nt][i] * alpha;
                    if (act) v = siluf(v);
                    C[(size_t)gr * Ncol + gc] = v;
                }
            }
        }
    }
}

// -------------- MLP third layer: out(E,OD) = H2(E,64) @ W3(64,OD) ----------
__global__ void mlp3_kernel(const float* __restrict__ H2,
                            const float* __restrict__ W3,
                            float* __restrict__ out, int OD) {
    int e = (blockIdx.x * blockDim.x + threadIdx.x) >> 5;
    int lane = threadIdx.x & 31;
    if (e >= EE) return;
    float v0 = H2[(size_t)e * 64 + lane];
    float v1 = H2[(size_t)e * 64 + lane + 32];
    for (int o = 0; o < OD; o++) {
        float p = v0 * W3[lane * OD + o] + v1 * W3[(lane + 32) * OD + o];
        p = warpSum(p);
        if (lane == 0) out[(size_t)e * OD + o] = p;
    }
}

// -------------- x = atom_table[node_atom] ----------------------------------
__global__ void embed_kernel(const float* __restrict__ atom_table,
                             const int* __restrict__ node_atom,
                             float* __restrict__ x) {
    int i = blockIdx.x * blockDim.x + threadIdx.x;
    if (i >= NN * DDIM) return;
    int n = i / DDIM, dd = i - n * DDIM;
    x[i] = atom_table[node_atom[n] * DDIM + dd];
}

// -------------- x += (sh@Wdeg)*g0 / sqrt(AVG_DEG), scattered to dst --------
__global__ void deg_kernel(const float* __restrict__ sh,
                           const float* __restrict__ Wdeg,
                           const float* __restrict__ g0,
                           const int* __restrict__ dst,
                           float* __restrict__ x, float scale) {
    int e = (blockIdx.x * blockDim.x + threadIdx.x) >> 5;
    int lane = threadIdx.x & 31;
    if (e >= EE) return;
    int d = dst[e];
    float shreg[SHN];
#pragma unroll
    for (int i = 0; i < SHN; i++) shreg[i] = sh[(size_t)e * SHN + i];
    float g = g0[e] * scale;
#pragma unroll
    for (int t = 0; t < 15; t++) {
        int dd = t * 32 + lane;
        float val = 0.f;
#pragma unroll
        for (int si = 0; si < SHN; si++) val += shreg[si] * Wdeg[si * DDIM + dd];
        atomicAdd(&x[(size_t)d * DDIM + dd], val * g);
    }
}

// -------------- per-layer init: agg=0, m=-inf, den=0 -----------------------
__global__ void init_layer_kernel(float* __restrict__ agg,
                                  float* __restrict__ m,
                                  float* __restrict__ den) {
    int i = blockIdx.x * blockDim.x + threadIdx.x;
    if (i < NN * DDIM) agg[i] = 0.f;
    if (i < NN * HH) {
        m[i] = __int_as_float(0xff800000);
        den[i] = 0.f;
    }
}

// -------------- logits[e,h] = inv*gate * q[dst]·(k[src]+sh@Wsh) ------------
__global__ void logits_kernel(const float* __restrict__ qn,
                              const float* __restrict__ kn,
                              const float* __restrict__ sh,
                              const float* __restrict__ Wsh_l,
                              const float* __restrict__ gate_l,
                              const int* __restrict__ src,
                              const int* __restrict__ dst,
                              float* __restrict__ logits,
                              float* __restrict__ m) {
    int e = (blockIdx.x * blockDim.x + threadIdx.x) >> 5;
    int lane = threadIdx.x & 31;
    if (e >= EE) return;
    int s = src[e], d = dst[e];
    float shreg[SHN];
#pragma unroll
    for (int i = 0; i < SHN; i++) shreg[i] = sh[(size_t)e * SHN + i];
    const float* qrow = qn + (size_t)d * DDIM;
    const float* krow = kn + (size_t)s * DDIM;
    const float inv = 0.09128709291752768f;
#pragma unroll
    for (int h = 0; h < HH; h++) {
        float acc = 0.f;
#pragma unroll
        for (int t = 0; t < 4; t++) {
            int j = t * 32 + lane;
            if (j < DHH) {
                int dd = h * DHH + j;
                float kv = krow[dd];
                float shk = 0.f;
#pragma unroll
                for (int si = 0; si < SHN; si++) shk += shreg[si] * Wsh_l[si * DDIM + dd];
                acc += qrow[dd] * (kv + shk);
            }
        }
        acc = warpSum(acc);
        if (lane == 0) {
            float lg = acc * inv * gate_l[(size_t)e * HH + h];
            logits[(size_t)e * HH + h] = lg;
            atomicMaxFloat(&m[(size_t)d * HH + h], lg);
        }
    }
}

// -------------- a = exp(logit - m[dst]); den[dst] += a ----------------------
__global__ void expden_kernel(float* __restrict__ logits,
                              const float* __restrict__ m,
                              float* __restrict__ den,
                              const int* __restrict__ dst) {
    int i = blockIdx.x * blockDim.x + threadIdx.x;
    if (i >= EE * HH) return;
    int e = i >> 2, h = i & 3;
    int d = dst[e];
    float a = expf(logits[i] - m[d * HH + h]);
    logits[i] = a;
    atomicAdd(&den[d * HH + h], a);
}

// -------------- agg[dst] += (a/den) * v[src] --------------------------------
__global__ void scatter_kernel(const float* __restrict__ a,
                               const float* __restrict__ den,
                               const float* __restrict__ vn,
                               const int* __restrict__ src,
                               const int* __restrict__ dst,
                               float* __restrict__ agg) {
    int e = (blockIdx.x * blockDim.x + threadIdx.x) >> 5;
    int lane = threadIdx.x & 31;
    if (e >= EE) return;
    int s = src[e], d = dst[e];
    float al[HH];
#pragma unroll
    for (int h = 0; h < HH; h++)
        al[h] = a[(size_t)e * HH + h] / (den[(size_t)d * HH + h] + 1e-12f);
    const float* vrow = vn + (size_t)s * DDIM;
    float* arow = agg + (size_t)d * DDIM;
#pragma unroll
    for (int t = 0; t < 15; t++) {
        int dd = t * 32 + lane;
        int h = dd / DHH;
        atomicAdd(&arow[dd], al[h] * vrow[dd]);
    }
}

// -------------- x = LayerNorm(x + y), row length 480 ------------------------
__global__ void ln_residual_kernel(float* __restrict__ x,
                                   const float* __restrict__ y) {
    int n = blockIdx.x;
    int tid = threadIdx.x;  // 128
    size_t base = (size_t)n * DDIM;
    float v[4];
    float s = 0.f;
#pragma unroll
    for (int t = 0; t < 4; t++) {
        int dd = tid + t * 128;
        v[t] = 0.f;
        if (dd < DDIM) {
            v[t] = x[base + dd] + y[base + dd];
            s += v[t];
        }
    }
    __shared__ float red[4];
    int wid = tid >> 5, lane = tid & 31;
    float ws = warpSum(s);
    if (lane == 0) red[wid] = ws;
    __syncthreads();
    float mean = (red[0] + red[1] + red[2] + red[3]) * (1.0f / DDIM);
    float vs = 0.f;
#pragma unroll
    for (int t = 0; t < 4; t++) {
        int dd = tid + t * 128;
        if (dd < DDIM) {
            float d0 = v[t] - mean;
            vs += d0 * d0;
        }
    }
    __syncthreads();
    float wv = warpSum(vs);
    if (lane == 0) red[wid] = wv;
    __syncthreads();
    float var = (red[0] + red[1] + red[2] + red[3]) * (1.0f / DDIM);
    float rstd = rsqrtf(var + 1e-5f);
#pragma unroll
    for (int t = 0; t < 4; t++) {
        int dd = tid + t * 128;
        if (dd < DDIM) x[base + dd] = (v[t] - mean) * rstd;
    }
}

// -------------- energy ------------------------------------------------------
__global__ void zero_out_kernel(float* __restrict__ out) {
    int i = threadIdx.x;
    if (i < GGG) out[i] = 0.f;
}

__global__ void energy_kernel(const float* __restrict__ hn,
                              const float* __restrict__ Wh2,
                              const int* __restrict__ batch,
                              float* __restrict__ out) {
    int n = (blockIdx.x * blockDim.x + threadIdx.x) >> 5;
    int lane = threadIdx.x & 31;
    if (n >= NN) return;
    float p = 0.f;
#pragma unroll
    for (int t = 0; t < 15; t++) {
        int dd = t * 32 + lane;
        p += hn[(size_t)n * DDIM + dd] * Wh2[dd];
    }
    p = warpSum(p);
    if (lane == 0) atomicAdd(&out[batch[n]], p * (1.0f / AVG_NODES_F));
}

// ------------------------- host orchestration -------------------------------
static void launch_gemm(const float* A, const float* B, float* C,
                        int M, int Ncol, int K, float alpha, int act) {
    dim3 grid((Ncol + BN - 1) / BN, (M + BM - 1) / BM);
    gemm_bf16x3_kernel<<<grid, 256>>>(A, B, C, M, Ncol, K, alpha, act);
}

extern "C" void kernel_launch(void* const* d_in, const int* in_sizes, int n_in,
                              void* d_out, int out_size) {
    const float *pos, *atom_table, *Wdeg, *Wd1, *Wd2, *Wd3, *Wq, *Wk, *Wv,
        *Wsh, *W1, *W2, *W3, *Wo, *Wf1, *Wf2, *Wh1, *Wh2;
    const int *node_atom, *edge_src, *edge_dst, *batch;

    if (in_sizes[1] == NN) {
        pos = (const float*)d_in[0];
        node_atom = (const int*)d_in[1];
        edge_src = (const int*)d_in[2];
        edge_dst = (const int*)d_in[3];
        batch = (const int*)d_in[4];
        atom_table = (const float*)d_in[5];
        Wdeg = (const float*)d_in[6];
        Wd1 = (const float*)d_in[7];
        Wd2 = (const float*)d_in[8];
        Wd3 = (const float*)d_in[9];
        Wq = (const float*)d_in[10];
        Wk = (const float*)d_in[11];
        Wv = (const float*)d_in[12];
        Wsh = (const float*)d_in[13];
        W1 = (const float*)d_in[14];
        W2 = (const float*)d_in[15];
        W3 = (const float*)d_in[16];
        Wo = (const float*)d_in[17];
        Wf1 = (const float*)d_in[18];
        Wf2 = (const float*)d_in[19];
        Wh1 = (const float*)d_in[20];
        Wh2 = (const float*)d_in[21];
    } else {
        pos = (const float*)d_in[0];
        atom_table = (const float*)d_in[1];
        Wdeg = (const float*)d_in[2];
        Wd1 = (const float*)d_in[3];
        Wd2 = (const float*)d_in[4];
        Wd3 = (const float*)d_in[5];
        Wq = (const float*)d_in[6];
        Wk = (const float*)d_in[7];
        Wv = (const float*)d_in[8];
        Wsh = (const float*)d_in[9];
        W1 = (const float*)d_in[10];
        W2 = (const float*)d_in[11];
        W3 = (const float*)d_in[12];
        Wo = (const float*)d_in[13];
        Wf1 = (const float*)d_in[14];
        Wf2 = (const float*)d_in[15];
        Wh1 = (const float*)d_in[16];
        Wh2 = (const float*)d_in[17];
        node_atom = (const int*)d_in[18];
        edge_src = (const int*)d_in[19];
        edge_dst = (const int*)d_in[20];
        batch = (const int*)d_in[21];
    }

    float* buf = nullptr;
    cudaGetSymbolAddress((void**)&buf, g_buf);
    float* sh = buf + O_SH;
    float* rbf = buf + O_RBF;
    float* g0 = buf + O_G0;
    float* gate = buf + O_GATE;
    float* x = buf + O_X;
    float* qn = buf + O_QN;
    float* kn = buf + O_KN;
    float* vn = buf + O_VN;
    float* agg = buf + O_AGG;
    float* tmp = buf + O_TMP;
    float* hn = buf + O_HN;
    float* hid = buf + O_HID;
    float* logits = buf + O_LOG;
    float* mbuf = buf + O_M;
    float* den = buf + O_DEN;
    float* eh1 = buf + O_EH1;
    float* eh2 = buf + O_EH2;
    float* out = (float*)d_out;

    const float invAvgDeg = (float)(1.0 / sqrt((double)AVG_DEG_F));

    const int warpBlocks = (EE * 32 + 255) / 256;
    const int ndBlocks = (NN * DDIM + 255) / 256;

    // ---- precompute (independent of x) ----
    edge_geom_kernel<<<warpBlocks, 256>>>(pos, edge_src, edge_dst, sh, rbf);

    launch_gemm(rbf, Wd1, eh1, EE, 64, NBB, 1.0f, 1);
    launch_gemm(eh1, Wd2, eh2, EE, 64, 64, 1.0f, 1);
    mlp3_kernel<<<warpBlocks, 256>>>(eh2, Wd3, g0, 1);

    for (int l = 0; l < LLAY; l++) {
        launch_gemm(rbf, W1 + (size_t)l * 128 * 64, eh1, EE, 64, NBB, 1.0f, 1);
        launch_gemm(eh1, W2 + (size_t)l * 64 * 64, eh2, EE, 64, 64, 1.0f, 1);
        mlp3_kernel<<<warpBlocks, 256>>>(eh2, W3 + (size_t)l * 64 * HH,
                                         gate + (size_t)l * EE * HH, HH);
    }

    // ---- node features ----
    embed_kernel<<<ndBlocks, 256>>>(atom_table, node_atom, x);
    deg_kernel<<<warpBlocks, 256>>>(sh, Wdeg, g0, edge_dst, x, invAvgDeg);

    // ---- transformer layers ----
    for (int l = 0; l < LLAY; l++) {
        const float* Wq_l = Wq + (size_t)l * DDIM * DDIM;
        const float* Wk_l = Wk + (size_t)l * DDIM * DDIM;
        const float* Wv_l = Wv + (size_t)l * DDIM * DDIM;
        const float* Wo_l = Wo + (size_t)l * DDIM * DDIM;
        const float* Wsh_l = Wsh + (size_t)l * SHN * DDIM;
        const float* Wf1_l = Wf1 + (size_t)l * DDIM * 2 * DDIM;
        const float* Wf2_l = Wf2 + (size_t)l * 2 * DDIM * DDIM;
        const float* gate_l = gate + (size_t)l * EE * HH;

        launch_gemm(x, Wq_l, qn, NN, DDIM, DDIM, 1.0f, 0);
        launch_gemm(x, Wk_l, kn, NN, DDIM, DDIM, 1.0f, 0);
        launch_gemm(x, Wv_l, vn, NN, DDIM, DDIM, 1.0f, 0);

        init_layer_kernel<<<ndBlocks, 256>>>(agg, mbuf, den);
        logits_kernel<<<warpBlocks, 256>>>(qn, kn, sh, Wsh_l, gate_l,
                                           edge_src, edge_dst, logits, mbuf);
        expden_kernel<<<(EE * HH + 255) / 256, 256>>>(logits, mbuf, den, edge_dst);
        scatter_kernel<<<warpBlocks, 256>>>(logits, den, vn, edge_src, edge_dst, agg);

        launch_gemm(agg, Wo_l, tmp, NN, DDIM, DDIM, invAvgDeg, 0);
        ln_residual_kernel<<<NN, 128>>>(x, tmp);

        launch_gemm(x, Wf1_l, hid, NN, 2 * DDIM, DDIM, 1.0f, 1);
        launch_gemm(hid, Wf2_l, tmp, NN, DDIM, 2 * DDIM, 1.0f, 0);
        ln_residual_kernel<<<NN, 128>>>(x, tmp);
    }

    // ---- readout ----
    launch_gemm(x, Wh1, hn, NN, DDIM, DDIM, 1.0f, 1);
    zero_out_kernel<<<1, 64>>>(out);
    energy_kernel<<<(NN * 32 + 255) / 256, 256>>>(hn, Wh2, batch, out);
}